// round 14
// baseline (speedup 1.0000x reference)
#include <cuda_runtime.h>
#include <cstdint>

#define Bb   4
#define NN   2048
#define FIN  256
#define FOUT 128
#define HH   4
#define NEG  0.2f
#define TKI  32          // j per mainloop iteration
#define NI   (NN / TKI)  // 64

// ---------------------------------------------------------------------------
// scratch (no cudaMalloc allowed)
// ---------------------------------------------------------------------------
__device__ float2   g_iAC[Bb * HH * NN];         // (e^el, e^.2el) per (b,h,i)
__device__ float2   g_jEFi[Bb * NN * HH];        // (e^er, e^.2er), [(b*NN+n)*4+h]
__device__ float2   g_irow[Bb * HH * NN];        // prescaled (A*0.25/Z, C*0.25/Z)
__device__ uint32_t g_adjbits[NN * 64];          // 512 KB
__device__ uint4    g_Bfrag4[Bb * (NN / 32) * 1024]; // Wh B-fragments (tf32)

// ---------------------------------------------------------------------------
__device__ __forceinline__ uint32_t f2tf32(float f) {
    uint32_t u;
    asm("cvt.rna.tf32.f32 %0, %1;" : "=r"(u) : "f"(f));
    return u;
}
__device__ __forceinline__ void mma_tf32(float& c0, float& c1, float& c2, float& c3,
                                         uint32_t a0, uint32_t a1, uint32_t a2, uint32_t a3,
                                         uint32_t b0, uint32_t b1) {
    asm volatile("mma.sync.aligned.m16n8k8.row.col.f32.tf32.tf32.f32 "
                 "{%0,%1,%2,%3}, {%4,%5,%6,%7}, {%8,%9}, {%0,%1,%2,%3};"
                 : "+f"(c0), "+f"(c1), "+f"(c2), "+f"(c3)
                 : "r"(a0), "r"(a1), "r"(a2), "r"(a3), "r"(b0), "r"(b1));
}
__device__ __forceinline__ void cp_async16(uint32_t dst, const void* src) {
    asm volatile("cp.async.cg.shared.global [%0], [%1], 16;" :: "r"(dst), "l"(src));
}
#define CP_COMMIT()  asm volatile("cp.async.commit_group;" ::: "memory")
#define CP_WAIT(n)   asm volatile("cp.async.wait_group %0;" :: "n"(n) : "memory")

// ---------------------------------------------------------------------------
// Kernel 0: adj -> bitmask
// ---------------------------------------------------------------------------
__global__ __launch_bounds__(64) void adjbits_kernel(const int* __restrict__ adj)
{
    const int row = blockIdx.x, w = threadIdx.x;
    const int4* p = (const int4*)(adj + (size_t)row * NN + w * 32);
    uint32_t bits = 0;
#pragma unroll
    for (int q = 0; q < 8; q++) {
        int4 v = __ldg(p + q);
        bits |= (v.x ? 1u : 0u) << (q * 4 + 0);
        bits |= (v.y ? 1u : 0u) << (q * 4 + 1);
        bits |= (v.z ? 1u : 0u) << (q * 4 + 2);
        bits |= (v.w ? 1u : 0u) << (q * 4 + 3);
    }
    g_adjbits[row * 64 + w] = bits;
}

// ---------------------------------------------------------------------------
// Kernel 1 (fused): Wh 16-row tile GEMM + half-Bfrag emit + el/er exps.
// grid 512 (3.46 CTAs/SM), 256 thr; thread = 2 rows x 4 cols.
// ---------------------------------------------------------------------------
__global__ __launch_bounds__(256) void wh_fused(const float* __restrict__ hsrc,
                                                const float* __restrict__ Ww,
                                                const float* __restrict__ Wb,
                                                const float* __restrict__ attn_w)
{
    __shared__ float Bs[32][128];    // Ww^T slab (per kb)  16 KB
    __shared__ float Whs[16][128];   // output tile          8 KB
    const int t     = threadIdx.x;
    const int grow0 = blockIdx.x * 16;
    const int col   = (t & 31) * 4;
    const int rl0   = (t >> 5) * 2;  // 2 rows per thread

    float acc[2][4];
#pragma unroll
    for (int r = 0; r < 2; r++)
#pragma unroll
        for (int c = 0; c < 4; c++) acc[r][c] = 0.f;

    const float* hr0 = hsrc + (size_t)(grow0 + rl0 + 0) * FIN;
    const float* hr1 = hsrc + (size_t)(grow0 + rl0 + 1) * FIN;

    for (int kb = 0; kb < FIN; kb += 32) {
        {
            int o = t >> 1, kh = (t & 1) * 16;
#pragma unroll
            for (int s2 = 0; s2 < 4; s2++) {
                float4 v = __ldg((const float4*)(Ww + (size_t)o * FIN + kb + kh + s2 * 4));
                Bs[kh + s2 * 4 + 0][o] = v.x;
                Bs[kh + s2 * 4 + 1][o] = v.y;
                Bs[kh + s2 * 4 + 2][o] = v.z;
                Bs[kh + s2 * 4 + 3][o] = v.w;
            }
        }
        __syncthreads();
#pragma unroll
        for (int k4 = 0; k4 < 32; k4 += 4) {
            float4 a0 = __ldg((const float4*)(hr0 + kb + k4));
            float4 a1 = __ldg((const float4*)(hr1 + kb + k4));
            float4 b0 = *(const float4*)&Bs[k4 + 0][col];
            float4 b1 = *(const float4*)&Bs[k4 + 1][col];
            float4 b2 = *(const float4*)&Bs[k4 + 2][col];
            float4 b3 = *(const float4*)&Bs[k4 + 3][col];
#define FMA2(ar, bv) \
            acc[0][0] += a0.ar * bv.x; acc[0][1] += a0.ar * bv.y; \
            acc[0][2] += a0.ar * bv.z; acc[0][3] += a0.ar * bv.w; \
            acc[1][0] += a1.ar * bv.x; acc[1][1] += a1.ar * bv.y; \
            acc[1][2] += a1.ar * bv.z; acc[1][3] += a1.ar * bv.w;
            FMA2(x, b0) FMA2(y, b1) FMA2(z, b2) FMA2(w, b3)
#undef FMA2
        }
        __syncthreads();
    }

    {
        float4 bias = __ldg((const float4*)(Wb + col));
#pragma unroll
        for (int r = 0; r < 2; r++) {
            float4 o4 = make_float4(acc[r][0] + bias.x, acc[r][1] + bias.y,
                                    acc[r][2] + bias.z, acc[r][3] + bias.w);
            *(float4*)&Whs[rl0 + r][col] = o4;
        }
    }
    __syncthreads();

    const int b    = grow0 >> 11;
    const int n0   = grow0 & (NN - 1);
    const int half = (n0 >> 4) & 1;     // which 16-row half of the 32-j bfrag tile

    // (a) emit half of the B-fragment tile (ks = 2*half, 2*half+1)
    {
        const size_t base = ((size_t)b * (NN / 32) + (n0 >> 5)) * 1024;
#pragma unroll
        for (int q = 0; q < 2; q++) {
            const int s    = half * 512 + q * 256 + t;
            const int lane = s & 31;
            const int ntp  = (s >> 5) & 7;
            const int ks   = s >> 8;
            const int jl   = ks * 8 + (lane & 3) - half * 16;   // local row 0..15
            const int o0   = ntp * 16 + (lane >> 2);
            g_Bfrag4[base + s] = make_uint4(f2tf32(Whs[jl][o0]),
                                            f2tf32(Whs[jl + 4][o0]),
                                            f2tf32(Whs[jl][o0 + 8]),
                                            f2tf32(Whs[jl + 4][o0 + 8]));
        }
    }

    // (b) el/er dots + exps (exact fp32): 8 warps x 2 rows
    {
        const int w    = t >> 5;
        const int lane = t & 31;
        float4 al[HH], ar[HH];
#pragma unroll
        for (int hh = 0; hh < HH; hh++) {
            al[hh] = __ldg((const float4*)(attn_w + hh * 2 * FOUT + lane * 4));
            ar[hh] = __ldg((const float4*)(attn_w + hh * 2 * FOUT + FOUT + lane * 4));
        }
#pragma unroll
        for (int r = 0; r < 2; r++) {
            const int rowl = w * 2 + r;
            const int n    = n0 + rowl;
            float4 v = *(const float4*)&Whs[rowl][lane * 4];
#pragma unroll
            for (int hh = 0; hh < HH; hh++) {
                float sl = v.x * al[hh].x + v.y * al[hh].y
                         + v.z * al[hh].z + v.w * al[hh].w;
                float sr = v.x * ar[hh].x + v.y * ar[hh].y
                         + v.z * ar[hh].z + v.w * ar[hh].w;
#pragma unroll
                for (int off = 16; off > 0; off >>= 1) {
                    sl += __shfl_xor_sync(0xffffffffu, sl, off);
                    sr += __shfl_xor_sync(0xffffffffu, sr, off);
                }
                if (lane == 0) {
                    g_iAC[(b * HH + hh) * NN + n] =
                        make_float2(expf(sl), expf(NEG * sl));
                    g_jEFi[((size_t)(b * NN + n)) * HH + hh] =
                        make_float2(expf(sr), expf(NEG * sr));
                }
            }
        }
    }
}

// ---------------------------------------------------------------------------
// Kernel 2: Z pre-pass (smem-tiled j-stream, max-trick).
// ---------------------------------------------------------------------------
__device__ __forceinline__ uint32_t zswz(uint32_t a) {
    return a ^ (((a >> 10) & 7u) << 5);
}
__global__ __launch_bounds__(256) void zsum_kernel()
{
    __shared__ float4 jef[512];
    __shared__ float  zr[32][4][8];
    const int t  = threadIdx.x;
    const int b  = blockIdx.y;
    const int i0 = blockIdx.x * 32;
    const int i  = t >> 3, jq = t & 7;
    const int gi = i0 + i;

    float2 AC[4];
#pragma unroll
    for (int h = 0; h < HH; h++) AC[h] = __ldg(&g_iAC[(b * HH + h) * NN + gi]);

    float z0 = 0.f, z1 = 0.f, z2 = 0.f, z3 = 0.f;
    const float4*   src4 = (const float4*)(g_jEFi + (size_t)b * NN * HH);
    const uint32_t* mrow = g_adjbits + (size_t)gi * 64;
    char* jefc = (char*)jef;

    for (int c0 = 0; c0 < NN; c0 += 256) {
        __syncthreads();
        {
            float4 v0 = __ldg(src4 + (size_t)(c0 + t) * 2);
            float4 v1 = __ldg(src4 + (size_t)(c0 + t) * 2 + 1);
            uint32_t a = zswz((uint32_t)t * 32u);
            *(float4*)(jefc + a)      = v0;
            *(float4*)(jefc + a + 16) = v1;
        }
        __syncthreads();

        const uint32_t mw = __ldg(mrow + (c0 >> 5) + jq);
#pragma unroll 8
        for (int e = 0; e < 32; e++) {
            if ((mw >> e) & 1u) {
                uint32_t a = zswz((uint32_t)(jq * 32 + e) * 32u);
                float4 q01 = *(const float4*)(jefc + a);
                float4 q23 = *(const float4*)(jefc + a + 16);
                z0 += fmaxf(AC[0].x * q01.x, AC[0].y * q01.y);
                z1 += fmaxf(AC[1].x * q01.z, AC[1].y * q01.w);
                z2 += fmaxf(AC[2].x * q23.x, AC[2].y * q23.y);
                z3 += fmaxf(AC[3].x * q23.z, AC[3].y * q23.w);
            }
        }
    }
    __syncthreads();
    zr[i][0][jq] = z0; zr[i][1][jq] = z1; zr[i][2][jq] = z2; zr[i][3][jq] = z3;
    __syncthreads();

    if (t < 128) {
        const int ii = t >> 2, h = t & 3;
        float Z = 0.f;
#pragma unroll
        for (int g = 0; g < 8; g++) Z += zr[ii][h][g];
        float2 ac  = __ldg(&g_iAC[(b * HH + h) * NN + i0 + ii]);
        float  inv = (Z > 0.f) ? 0.25f / Z : 0.f;
        g_irow[(b * HH + h) * NN + i0 + ii] = make_float2(ac.x * inv, ac.y * inv);
    }
}

// ---------------------------------------------------------------------------
// Kernel 3 (main): P_avg @ Wh via mma.sync tf32. ONE barrier per iteration.
// Af triple-buffered (regs->smem), B/JP quad-buffered (cp.async 2 ahead).
// iter jt: stage(jt+2); wait; agen(jt+1); SYNC; consume(jt).
// smem 80KB: Af 3x4K | Bf 4x16K | JP 4x1K. 2 CTAs/SM.
// ---------------------------------------------------------------------------
#define SM_A(s, mt, ks, ln)  ((s) * 256 + ((mt) * 4 + (ks)) * 32 + (ln))
#define SM_B(p, ks, ntp, ln) ((p) * 1024 + (ks) * 256 + (ntp) * 32 + (ln))
#define OFF_BF 12288
#define OFF_JP (12288 + 4 * 16384)        // 77824
#define SMEM_BYTES (OFF_JP + 4 * 1024)    // 81920

__global__ __launch_bounds__(256, 2) void gat_main_mma(float* __restrict__ out)
{
    extern __shared__ char smem[];
    uint4*  Af  = (uint4*)smem;
    uint4*  Bf  = (uint4*)(smem + OFF_BF);
    float4* JPf = (float4*)(smem + OFF_JP);
    const uint32_t Bf_sa = (uint32_t)__cvta_generic_to_shared(Bf);
    const uint32_t JP_sa = (uint32_t)__cvta_generic_to_shared(JPf);

    const int t    = threadIdx.x;
    const int w    = t >> 5;
    const int lane = t & 31;
    const int mw   = w >> 2;            // m16 tile (gen + consume)
    const int nw   = w & 3;             // consume: 32-col group; gen: ks
    const int b    = blockIdx.y;
    const int i0   = blockIdx.x * 32;

    const int r = lane >> 2;
    const int c = lane & 3;

    const int gia = i0 + mw * 16 + r;
    const int gib = gia + 8;

    float2 RA[4], RB[4];
#pragma unroll
    for (int h = 0; h < HH; h++) {
        RA[h] = __ldg(&g_irow[(b * HH + h) * NN + gia]);
        RB[h] = __ldg(&g_irow[(b * HH + h) * NN + gib]);
    }
    const uint32_t* mba   = g_adjbits + (size_t)gia * 64;
    const uint32_t* mbb   = g_adjbits + (size_t)gib * 64;
    const uint4*    bbase = g_Bfrag4 + (size_t)b * (NN / 32) * 1024;
    const float4*   jsrc  = (const float4*)(g_jEFi + (size_t)b * NN * HH);

    float acc[4][4];
#pragma unroll
    for (int n = 0; n < 4; n++)
#pragma unroll
        for (int k = 0; k < 4; k++) acc[n][k] = 0.f;

    auto stage = [&](int jn) {
        const int q = jn & 3;
        const uint4* src = bbase + (size_t)jn * 1024;
        const uint32_t bdst = Bf_sa + (uint32_t)q * 16384u;
#pragma unroll
        for (int k4 = 0; k4 < 4; k4++)
            cp_async16(bdst + (uint32_t)(k4 * 256 + t) * 16u, src + k4 * 256 + t);
        if (t < 64)
            cp_async16(JP_sa + (uint32_t)(q * 64 + t) * 16u, jsrc + jn * 64 + t);
        CP_COMMIT();
    };

    // warp (mw, nw) generates fragment (mt=mw, ks=nw) of tile jn into Af[jn%3]
    auto agen = [&](int jn, uint32_t ma, uint32_t mb2) {
        const float4* JP = JPf + (jn & 3) * 64;
        const int jA = nw * 8 + c;
        float4 a01 = JP[jA * 2],       a23 = JP[jA * 2 + 1];
        float4 b01 = JP[(jA + 4) * 2], b23 = JP[(jA + 4) * 2 + 1];

        float vaA = (fmaxf(RA[0].x * a01.x, RA[0].y * a01.y)
                   + fmaxf(RA[1].x * a01.z, RA[1].y * a01.w))
                  + (fmaxf(RA[2].x * a23.x, RA[2].y * a23.y)
                   + fmaxf(RA[3].x * a23.z, RA[3].y * a23.w));
        float vbA = (fmaxf(RB[0].x * a01.x, RB[0].y * a01.y)
                   + fmaxf(RB[1].x * a01.z, RB[1].y * a01.w))
                  + (fmaxf(RB[2].x * a23.x, RB[2].y * a23.y)
                   + fmaxf(RB[3].x * a23.z, RB[3].y * a23.w));
        float vaB = (fmaxf(RA[0].x * b01.x, RA[0].y * b01.y)
                   + fmaxf(RA[1].x * b01.z, RA[1].y * b01.w))
                  + (fmaxf(RA[2].x * b23.x, RA[2].y * b23.y)
                   + fmaxf(RA[3].x * b23.z, RA[3].y * b23.w));
        float vbB = (fmaxf(RB[0].x * b01.x, RB[0].y * b01.y)
                   + fmaxf(RB[1].x * b01.z, RB[1].y * b01.w))
                  + (fmaxf(RB[2].x * b23.x, RB[2].y * b23.y)
                   + fmaxf(RB[3].x * b23.z, RB[3].y * b23.w));

        const int sh = nw * 8 + c;
        vaA = ((ma  >> sh)       & 1u) ? vaA : 0.f;
        vbA = ((mb2 >> sh)       & 1u) ? vbA : 0.f;
        vaB = ((ma  >> (sh + 4)) & 1u) ? vaB : 0.f;
        vbB = ((mb2 >> (sh + 4)) & 1u) ? vbB : 0.f;

        Af[SM_A(jn % 3, mw, nw, lane)] =
            make_uint4(f2tf32(vaA), f2tf32(vbA), f2tf32(vaB), f2tf32(vbB));
    };

    auto consume = [&](int jn) {
        const int s = jn % 3, p = jn & 3;
#pragma unroll
        for (int ks = 0; ks < 4; ks++) {
            uint4 a  = Af[SM_A(s, mw, ks, lane)];
            uint4 b0 = Bf[SM_B(p, ks, nw * 2 + 0, lane)];
            uint4 b1 = Bf[SM_B(p, ks, nw * 2 + 1, lane)];
            mma_tf32(acc[0][0], acc[0][1], acc[0][2], acc[0][3],
                     a.x, a.y, a.z, a.w, b0.x, b0.y);
            mma_tf32(acc[1][0], acc[1][1], acc[1][2], acc[1][3],
                     a.x, a.y, a.z, a.w, b0.z, b0.w);
            mma_tf32(acc[2][0], acc[2][1], acc[2][2], acc[2][3],
                     a.x, a.y, a.z, a.w, b1.x, b1.y);
            mma_tf32(acc[3][0], acc[3][1], acc[3][2], acc[3][3],
                     a.x, a.y, a.z, a.w, b1.z, b1.w);
        }
    };

    // ---- prologue: tiles 0,1 staged; agen(0) done ----
    stage(0);
    stage(1);
    uint32_t ma0 = __ldg(mba + 0), mb0 = __ldg(mbb + 0);
    uint32_t ma1 = __ldg(mba + 1), mb1 = __ldg(mbb + 1);
    CP_WAIT(1);                      // tile 0 complete
    __syncthreads();                 // cp visibility
    agen(0, ma0, mb0);
    __syncthreads();                 // Af[0] visible

    // ---- single-sync mainloop ----
    for (int jt = 0; jt < NI; jt++) {
        if (jt + 2 < NI) stage(jt + 2);

        if (jt + 1 < NI) {
            if (jt + 2 < NI) CP_WAIT(1);   // tile jt+1 done, jt+2 may fly
            else             CP_WAIT(0);   // last tile: drain
            agen(jt + 1, ma1, mb1);
            if (jt + 2 < NI) {
                ma1 = __ldg(mba + jt + 2);
                mb1 = __ldg(mbb + jt + 2);
            }
        }

        __syncthreads();                   // ONE barrier per iteration

        consume(jt);
    }

    // epilogue: accumulators are final pre-ReLU outputs
    const int rowa = i0 + mw * 16 + r;
#pragma unroll
    for (int nt = 0; nt < 4; nt++) {
        const int col = nw * 32 + nt * 8 + c * 2;
        float* op = out + ((size_t)(b * NN + rowa)) * FOUT + col;
        *(float2*)op = make_float2(fmaxf(acc[nt][0], 0.f), fmaxf(acc[nt][1], 0.f));
        *(float2*)(op + 8 * FOUT) = make_float2(fmaxf(acc[nt][2], 0.f),
                                                fmaxf(acc[nt][3], 0.f));
    }
}

// ---------------------------------------------------------------------------
extern "C" void kernel_launch(void* const* d_in, const int* in_sizes, int n_in,
                              void* d_out, int out_size)
{
    const float* h      = (const float*)d_in[0];
    const int*   adj    = (const int*)d_in[1];
    const float* W_w    = (const float*)d_in[2];
    const float* W_b    = (const float*)d_in[3];
    const float* attn_w = (const float*)d_in[4];
    float* out = (float*)d_out;

    adjbits_kernel<<<NN, 64>>>(adj);
    wh_fused<<<(Bb * NN) / 16, 256>>>(h, W_w, W_b, attn_w);
    zsum_kernel<<<dim3(NN / 32, Bb), 256>>>();

    cudaFuncSetAttribute(gat_main_mma,
                         cudaFuncAttributeMaxDynamicSharedMemorySize, SMEM_BYTES);
    gat_main_mma<<<dim3(NN / 32, Bb), 256, SMEM_BYTES>>>(out);
}

// round 16
// speedup vs baseline: 1.2555x; 1.2555x over previous
#include <cuda_runtime.h>
#include <cstdint>

#define Bb   4
#define NN   2048
#define FIN  256
#define FOUT 128
#define HH   4
#define NEG  0.2f
#define TKI  32          // j per mainloop iteration
#define NI   (NN / TKI)  // 64

// ---------------------------------------------------------------------------
// scratch (no cudaMalloc allowed)
// ---------------------------------------------------------------------------
__device__ float2   g_iAC[Bb * HH * NN];         // (e^el, e^.2el) per (b,h,i)
__device__ float2   g_jEFi[Bb * NN * HH];        // (e^er, e^.2er), [(b*NN+n)*4+h]
__device__ float2   g_irow[Bb * HH * NN];        // prescaled (A*0.25/Z, C*0.25/Z)
__device__ uint32_t g_adjbits[NN * 64];          // 512 KB
__device__ uint4    g_Bfrag4[Bb * (NN / 32) * 1024]; // Wh B-fragments (tf32)
__device__ uint4    g_Wwfrag[(FIN / 8) * 256];   // Ww B-fragments (tf32), 128 KB

// ---------------------------------------------------------------------------
__device__ __forceinline__ uint32_t f2tf32(float f) {
    uint32_t u;
    asm("cvt.rna.tf32.f32 %0, %1;" : "=r"(u) : "f"(f));
    return u;
}
__device__ __forceinline__ void mma_tf32(float& c0, float& c1, float& c2, float& c3,
                                         uint32_t a0, uint32_t a1, uint32_t a2, uint32_t a3,
                                         uint32_t b0, uint32_t b1) {
    asm volatile("mma.sync.aligned.m16n8k8.row.col.f32.tf32.tf32.f32 "
                 "{%0,%1,%2,%3}, {%4,%5,%6,%7}, {%8,%9}, {%0,%1,%2,%3};"
                 : "+f"(c0), "+f"(c1), "+f"(c2), "+f"(c3)
                 : "r"(a0), "r"(a1), "r"(a2), "r"(a3), "r"(b0), "r"(b1));
}
__device__ __forceinline__ void cp_async16(uint32_t dst, const void* src) {
    asm volatile("cp.async.cg.shared.global [%0], [%1], 16;" :: "r"(dst), "l"(src));
}
#define CP_COMMIT() asm volatile("cp.async.commit_group;" ::: "memory")
#define CP_WAIT0()  asm volatile("cp.async.wait_group 0;" ::: "memory")

// ---------------------------------------------------------------------------
// Kernel 0: adj -> bitmask
// ---------------------------------------------------------------------------
__global__ __launch_bounds__(64) void adjbits_kernel(const int* __restrict__ adj)
{
    const int row = blockIdx.x, w = threadIdx.x;
    const int4* p = (const int4*)(adj + (size_t)row * NN + w * 32);
    uint32_t bits = 0;
#pragma unroll
    for (int q = 0; q < 8; q++) {
        int4 v = __ldg(p + q);
        bits |= (v.x ? 1u : 0u) << (q * 4 + 0);
        bits |= (v.y ? 1u : 0u) << (q * 4 + 1);
        bits |= (v.z ? 1u : 0u) << (q * 4 + 2);
        bits |= (v.w ? 1u : 0u) << (q * 4 + 3);
    }
    g_adjbits[row * 64 + w] = bits;
}

// ---------------------------------------------------------------------------
// Kernel 0b: Ww -> tf32 B-fragments. slot s = ks*256 + ntp*32 + lane:
//   n0 = ntp*16 + lane/4 (and n0+8), k0 = ks*8 + (lane&3) (and k0+4)
//   uint4 = {Ww[n0][k0], Ww[n0][k0+4], Ww[n0+8][k0], Ww[n0+8][k0+4]}
// ---------------------------------------------------------------------------
__global__ __launch_bounds__(256) void wwfrag_kernel(const float* __restrict__ Ww)
{
    const int ks = blockIdx.x, t = threadIdx.x;
    const int lane = t & 31, ntp = t >> 5;
    const int n0 = ntp * 16 + (lane >> 2);
    const int k0 = ks * 8 + (lane & 3);
    g_Wwfrag[ks * 256 + t] = make_uint4(
        f2tf32(__ldg(Ww + (size_t)n0 * FIN + k0)),
        f2tf32(__ldg(Ww + (size_t)n0 * FIN + k0 + 4)),
        f2tf32(__ldg(Ww + (size_t)(n0 + 8) * FIN + k0)),
        f2tf32(__ldg(Ww + (size_t)(n0 + 8) * FIN + k0 + 4)));
}

// ---------------------------------------------------------------------------
// Kernel 1 (fused, TENSOR-CORE): Wh = h @ Ww^T + b via tf32 mma,
// then emit main-GEMM B-fragments + el/er exps. 256 blocks x 256 thr.
// Warp (mw = w>>2, nw = w&3): rows mw*16..+15, cols nw*32..+31.
// ---------------------------------------------------------------------------
__global__ __launch_bounds__(256) void wh_fused_tc(const float* __restrict__ hsrc,
                                                   const float* __restrict__ Wb,
                                                   const float* __restrict__ attn_w)
{
    __shared__ uint32_t hs[32][260];   // h tile, tf32 bits, padded (33.3 KB)
    __shared__ float    Whs[32][128];  // output tile (16 KB)
    const int t     = threadIdx.x;
    const int w     = t >> 5;
    const int lane  = t & 31;
    const int mw    = w >> 2;
    const int nw    = w & 3;
    const int r     = lane >> 2;
    const int c     = lane & 3;
    const int grow0 = blockIdx.x * 32;

    // stage h tile (coalesced), convert to tf32
    {
        const int row = t >> 3;
        const float4* src = (const float4*)(hsrc + (size_t)(grow0 + row) * FIN);
#pragma unroll
        for (int q = 0; q < 8; q++) {
            float4 v = __ldg(src + q * 8 + (t & 7));
            const int col = q * 32 + (t & 7) * 4;
            hs[row][col + 0] = f2tf32(v.x);
            hs[row][col + 1] = f2tf32(v.y);
            hs[row][col + 2] = f2tf32(v.z);
            hs[row][col + 3] = f2tf32(v.w);
        }
    }
    __syncthreads();

    float acc[4][4];
#pragma unroll
    for (int n = 0; n < 4; n++)
#pragma unroll
        for (int k = 0; k < 4; k++) acc[n][k] = 0.f;

    const int mrow = mw * 16 + r;
    const uint4* wwb = g_Wwfrag;

#pragma unroll 8
    for (int ks = 0; ks < FIN / 8; ks++) {
        const int kc = ks * 8 + c;
        uint32_t a0 = hs[mrow][kc];
        uint32_t a1 = hs[mrow + 8][kc];
        uint32_t a2 = hs[mrow][kc + 4];
        uint32_t a3 = hs[mrow + 8][kc + 4];
        uint4 b0 = __ldg(wwb + ks * 256 + (nw * 2 + 0) * 32 + lane);
        uint4 b1 = __ldg(wwb + ks * 256 + (nw * 2 + 1) * 32 + lane);
        mma_tf32(acc[0][0], acc[0][1], acc[0][2], acc[0][3],
                 a0, a1, a2, a3, b0.x, b0.y);
        mma_tf32(acc[1][0], acc[1][1], acc[1][2], acc[1][3],
                 a0, a1, a2, a3, b0.z, b0.w);
        mma_tf32(acc[2][0], acc[2][1], acc[2][2], acc[2][3],
                 a0, a1, a2, a3, b1.x, b1.y);
        mma_tf32(acc[3][0], acc[3][1], acc[3][2], acc[3][3],
                 a0, a1, a2, a3, b1.z, b1.w);
    }

    // bias + store to Whs
#pragma unroll
    for (int nt = 0; nt < 4; nt++) {
        const int col = nw * 32 + nt * 8 + c * 2;
        float2 bias = *(const float2*)(Wb + col);
        Whs[mrow][col + 0]     = acc[nt][0] + bias.x;
        Whs[mrow][col + 1]     = acc[nt][1] + bias.y;
        Whs[mrow + 8][col + 0] = acc[nt][2] + bias.x;
        Whs[mrow + 8][col + 1] = acc[nt][3] + bias.y;
    }
    __syncthreads();

    const int b  = grow0 >> 11;
    const int n0 = grow0 & (NN - 1);

    // (a) emit main-GEMM B-fragments (tf32)
    {
        const size_t base = ((size_t)b * (NN / 32) + (n0 >> 5)) * 1024;
#pragma unroll
        for (int q = 0; q < 4; q++) {
            const int s    = q * 256 + t;
            const int ln   = s & 31;
            const int ntp  = (s >> 5) & 7;
            const int ks   = s >> 8;
            const int jl   = ks * 8 + (ln & 3);
            const int o0   = ntp * 16 + (ln >> 2);
            g_Bfrag4[base + s] = make_uint4(f2tf32(Whs[jl][o0]),
                                            f2tf32(Whs[jl + 4][o0]),
                                            f2tf32(Whs[jl][o0 + 8]),
                                            f2tf32(Whs[jl + 4][o0 + 8]));
        }
    }

    // (b) el/er dots + exps (fp32)
    {
        float4 al[HH], ar[HH];
#pragma unroll
        for (int hh = 0; hh < HH; hh++) {
            al[hh] = __ldg((const float4*)(attn_w + hh * 2 * FOUT + lane * 4));
            ar[hh] = __ldg((const float4*)(attn_w + hh * 2 * FOUT + FOUT + lane * 4));
        }
#pragma unroll
        for (int rr = 0; rr < 4; rr++) {
            const int rowl = w * 4 + rr;
            const int n    = n0 + rowl;
            float4 v = *(const float4*)&Whs[rowl][lane * 4];
#pragma unroll
            for (int hh = 0; hh < HH; hh++) {
                float sl = v.x * al[hh].x + v.y * al[hh].y
                         + v.z * al[hh].z + v.w * al[hh].w;
                float sr = v.x * ar[hh].x + v.y * ar[hh].y
                         + v.z * ar[hh].z + v.w * ar[hh].w;
#pragma unroll
                for (int off = 16; off > 0; off >>= 1) {
                    sl += __shfl_xor_sync(0xffffffffu, sl, off);
                    sr += __shfl_xor_sync(0xffffffffu, sr, off);
                }
                if (lane == 0) {
                    g_iAC[(b * HH + hh) * NN + n] =
                        make_float2(expf(sl), expf(NEG * sl));
                    g_jEFi[((size_t)(b * NN + n)) * HH + hh] =
                        make_float2(expf(sr), expf(NEG * sr));
                }
            }
        }
    }
}

// ---------------------------------------------------------------------------
// Kernel 2: Z pre-pass (smem-tiled j-stream, max-trick).
// ---------------------------------------------------------------------------
__device__ __forceinline__ uint32_t zswz(uint32_t a) {
    return a ^ (((a >> 10) & 7u) << 5);
}
__global__ __launch_bounds__(256) void zsum_kernel()
{
    __shared__ float4 jef[512];
    __shared__ float  zr[32][4][8];
    const int t  = threadIdx.x;
    const int b  = blockIdx.y;
    const int i0 = blockIdx.x * 32;
    const int i  = t >> 3, jq = t & 7;
    const int gi = i0 + i;

    float2 AC[4];
#pragma unroll
    for (int h = 0; h < HH; h++) AC[h] = __ldg(&g_iAC[(b * HH + h) * NN + gi]);

    float z0 = 0.f, z1 = 0.f, z2 = 0.f, z3 = 0.f;
    const float4*   src4 = (const float4*)(g_jEFi + (size_t)b * NN * HH);
    const uint32_t* mrow = g_adjbits + (size_t)gi * 64;
    char* jefc = (char*)jef;

    for (int c0 = 0; c0 < NN; c0 += 256) {
        __syncthreads();
        {
            float4 v0 = __ldg(src4 + (size_t)(c0 + t) * 2);
            float4 v1 = __ldg(src4 + (size_t)(c0 + t) * 2 + 1);
            uint32_t a = zswz((uint32_t)t * 32u);
            *(float4*)(jefc + a)      = v0;
            *(float4*)(jefc + a + 16) = v1;
        }
        __syncthreads();

        const uint32_t mw = __ldg(mrow + (c0 >> 5) + jq);
#pragma unroll 8
        for (int e = 0; e < 32; e++) {
            if ((mw >> e) & 1u) {
                uint32_t a = zswz((uint32_t)(jq * 32 + e) * 32u);
                float4 q01 = *(const float4*)(jefc + a);
                float4 q23 = *(const float4*)(jefc + a + 16);
                z0 += fmaxf(AC[0].x * q01.x, AC[0].y * q01.y);
                z1 += fmaxf(AC[1].x * q01.z, AC[1].y * q01.w);
                z2 += fmaxf(AC[2].x * q23.x, AC[2].y * q23.y);
                z3 += fmaxf(AC[3].x * q23.z, AC[3].y * q23.w);
            }
        }
    }
    __syncthreads();
    zr[i][0][jq] = z0; zr[i][1][jq] = z1; zr[i][2][jq] = z2; zr[i][3][jq] = z3;
    __syncthreads();

    if (t < 128) {
        const int ii = t >> 2, h = t & 3;
        float Z = 0.f;
#pragma unroll
        for (int g = 0; g < 8; g++) Z += zr[ii][h][g];
        float2 ac  = __ldg(&g_iAC[(b * HH + h) * NN + i0 + ii]);
        float  inv = (Z > 0.f) ? 0.25f / Z : 0.f;
        g_irow[(b * HH + h) * NN + i0 + ii] = make_float2(ac.x * inv, ac.y * inv);
    }
}

// ---------------------------------------------------------------------------
// Kernel 3 (main): P_avg @ Wh via mma.sync tf32, M=32, TK=32/iter. (R10 best)
// ---------------------------------------------------------------------------
#define SM_A(mt, ks, ln)    (((mt) * 4 + (ks)) * 32 + (ln))
#define SM_B(p, ks, ntp, ln) ((p) * 1024 + (ks) * 256 + (ntp) * 32 + (ln))
#define OFF_BF 4096
#define OFF_JP 36864
#define SMEM_BYTES 38912

__global__ __launch_bounds__(256, 3) void gat_main_mma(float* __restrict__ out)
{
    extern __shared__ char smem[];
    uint4*  Af  = (uint4*)smem;
    uint4*  Bf  = (uint4*)(smem + OFF_BF);
    float4* JPf = (float4*)(smem + OFF_JP);
    const uint32_t Bf_sa = (uint32_t)__cvta_generic_to_shared(Bf);
    const uint32_t JP_sa = (uint32_t)__cvta_generic_to_shared(JPf);

    const int t    = threadIdx.x;
    const int w    = t >> 5;
    const int lane = t & 31;
    const int mw   = w >> 2;
    const int nw   = w & 3;
    const int b    = blockIdx.y;
    const int i0   = blockIdx.x * 32;

    const int r = lane >> 2;
    const int c = lane & 3;

    const int gia = i0 + mw * 16 + r;
    const int gib = gia + 8;

    float2 RA[4], RB[4];
#pragma unroll
    for (int h = 0; h < HH; h++) {
        RA[h] = __ldg(&g_irow[(b * HH + h) * NN + gia]);
        RB[h] = __ldg(&g_irow[(b * HH + h) * NN + gib]);
    }
    const uint32_t* mba   = g_adjbits + (size_t)gia * 64;
    const uint32_t* mbb   = g_adjbits + (size_t)gib * 64;
    const uint4*    bbase = g_Bfrag4 + (size_t)b * (NN / 32) * 1024;
    const float4*   jsrc  = (const float4*)(g_jEFi + (size_t)b * NN * HH);

    float acc[4][4];
#pragma unroll
    for (int n = 0; n < 4; n++)
#pragma unroll
        for (int k = 0; k < 4; k++) acc[n][k] = 0.f;

    auto stage = [&](int jn, int q) {
        const uint4* src = bbase + (size_t)jn * 1024;
        const uint32_t bdst = Bf_sa + (uint32_t)q * 16384u;
#pragma unroll
        for (int k4 = 0; k4 < 4; k4++)
            cp_async16(bdst + (uint32_t)(k4 * 256 + t) * 16u, src + k4 * 256 + t);
        if (t < 64)
            cp_async16(JP_sa + (uint32_t)(q * 64 + t) * 16u, jsrc + jn * 64 + t);
        CP_COMMIT();
    };

    auto agen = [&](int p, uint32_t ma, uint32_t mb2) {
        const float4* JP = JPf + p * 64;
        const int jA = nw * 8 + c;
        float4 a01 = JP[jA * 2],       a23 = JP[jA * 2 + 1];
        float4 b01 = JP[(jA + 4) * 2], b23 = JP[(jA + 4) * 2 + 1];

        float vaA = (fmaxf(RA[0].x * a01.x, RA[0].y * a01.y)
                   + fmaxf(RA[1].x * a01.z, RA[1].y * a01.w))
                  + (fmaxf(RA[2].x * a23.x, RA[2].y * a23.y)
                   + fmaxf(RA[3].x * a23.z, RA[3].y * a23.w));
        float vbA = (fmaxf(RB[0].x * a01.x, RB[0].y * a01.y)
                   + fmaxf(RB[1].x * a01.z, RB[1].y * a01.w))
                  + (fmaxf(RB[2].x * a23.x, RB[2].y * a23.y)
                   + fmaxf(RB[3].x * a23.z, RB[3].y * a23.w));
        float vaB = (fmaxf(RA[0].x * b01.x, RA[0].y * b01.y)
                   + fmaxf(RA[1].x * b01.z, RA[1].y * b01.w))
                  + (fmaxf(RA[2].x * b23.x, RA[2].y * b23.y)
                   + fmaxf(RA[3].x * b23.z, RA[3].y * b23.w));
        float vbB = (fmaxf(RB[0].x * b01.x, RB[0].y * b01.y)
                   + fmaxf(RB[1].x * b01.z, RB[1].y * b01.w))
                  + (fmaxf(RB[2].x * b23.x, RB[2].y * b23.y)
                   + fmaxf(RB[3].x * b23.z, RB[3].y * b23.w));

        const int sh = nw * 8 + c;
        vaA = ((ma  >> sh)       & 1u) ? vaA : 0.f;
        vbA = ((mb2 >> sh)       & 1u) ? vbA : 0.f;
        vaB = ((ma  >> (sh + 4)) & 1u) ? vaB : 0.f;
        vbB = ((mb2 >> (sh + 4)) & 1u) ? vbB : 0.f;

        Af[SM_A(mw, nw, lane)] =
            make_uint4(f2tf32(vaA), f2tf32(vbA), f2tf32(vaB), f2tf32(vbB));
    };

    auto consume = [&](int p) {
#pragma unroll
        for (int ks = 0; ks < 4; ks++) {
            uint4 a  = Af[SM_A(mw, ks, lane)];
            uint4 b0 = Bf[SM_B(p, ks, nw * 2 + 0, lane)];
            uint4 b1 = Bf[SM_B(p, ks, nw * 2 + 1, lane)];
            mma_tf32(acc[0][0], acc[0][1], acc[0][2], acc[0][3],
                     a.x, a.y, a.z, a.w, b0.x, b0.y);
            mma_tf32(acc[1][0], acc[1][1], acc[1][2], acc[1][3],
                     a.x, a.y, a.z, a.w, b0.z, b0.w);
            mma_tf32(acc[2][0], acc[2][1], acc[2][2], acc[2][3],
                     a.x, a.y, a.z, a.w, b1.x, b1.y);
            mma_tf32(acc[3][0], acc[3][1], acc[3][2], acc[3][3],
                     a.x, a.y, a.z, a.w, b1.z, b1.w);
        }
    };

    stage(0, 0);
    uint32_t maC = __ldg(mba + 0);
    uint32_t mbC = __ldg(mbb + 0);
    CP_WAIT0();
    __syncthreads();

    for (int jt = 0; jt < NI; jt++) {
        const int p = jt & 1, q = p ^ 1;

        if (jt + 1 < NI) stage(jt + 1, q);

        agen(p, maC, mbC);
        __syncthreads();

        consume(p);

        if (jt + 1 < NI) {
            maC = __ldg(mba + jt + 1);
            mbC = __ldg(mbb + jt + 1);
            CP_WAIT0();
        }
        __syncthreads();
    }

    const int rowa = i0 + mw * 16 + r;
#pragma unroll
    for (int nt = 0; nt < 4; nt++) {
        const int col = nw * 32 + nt * 8 + c * 2;
        float* op = out + ((size_t)(b * NN + rowa)) * FOUT + col;
        *(float2*)op = make_float2(fmaxf(acc[nt][0], 0.f), fmaxf(acc[nt][1], 0.f));
        *(float2*)(op + 8 * FOUT) = make_float2(fmaxf(acc[nt][2], 0.f),
                                                fmaxf(acc[nt][3], 0.f));
    }
}

// ---------------------------------------------------------------------------
extern "C" void kernel_launch(void* const* d_in, const int* in_sizes, int n_in,
                              void* d_out, int out_size)
{
    const float* h      = (const float*)d_in[0];
    const int*   adj    = (const int*)d_in[1];
    const float* W_w    = (const float*)d_in[2];
    const float* W_b    = (const float*)d_in[3];
    const float* attn_w = (const float*)d_in[4];
    float* out = (float*)d_out;

    adjbits_kernel<<<NN, 64>>>(adj);
    wwfrag_kernel<<<FIN / 8, 256>>>(W_w);
    wh_fused_tc<<<(Bb * NN) / 32, 256>>>(h, W_b, attn_w);
    zsum_kernel<<<dim3(NN / 32, Bb), 256>>>();

    cudaFuncSetAttribute(gat_main_mma,
                         cudaFuncAttributeMaxDynamicSharedMemorySize, SMEM_BYTES);
    gat_main_mma<<<dim3(NN / 32, Bb), 256, SMEM_BYTES>>>(out);
}

// round 17
// speedup vs baseline: 1.4150x; 1.1270x over previous
#include <cuda_runtime.h>
#include <cstdint>

#define Bb   4
#define NN   2048
#define FIN  256
#define FOUT 128
#define HH   4
#define NEG  0.2f
#define TKI  32          // j per mainloop iteration
#define NI   (NN / TKI)  // 64

// ---------------------------------------------------------------------------
// scratch (no cudaMalloc allowed)
// ---------------------------------------------------------------------------
__device__ float2   g_iAC[Bb * HH * NN];         // (e^el, e^.2el) per (b,h,i)
__device__ float2   g_jEFi[Bb * NN * HH];        // (e^er, e^.2er), [(b*NN+n)*4+h]
__device__ float2   g_irow[Bb * HH * NN];        // prescaled (A*0.25/Z, C*0.25/Z)
__device__ uint32_t g_adjbits[NN * 64];          // 512 KB
__device__ uint4    g_Bfrag4[Bb * (NN / 32) * 1024]; // Wh B-fragments (tf32)
__device__ uint4    g_Wwfrag[(FIN / 8) * 256];   // Ww B-fragments (tf32), 128 KB

// ---------------------------------------------------------------------------
__device__ __forceinline__ uint32_t f2tf32(float f) {
    uint32_t u;
    asm("cvt.rna.tf32.f32 %0, %1;" : "=r"(u) : "f"(f));
    return u;
}
__device__ __forceinline__ void mma_tf32(float& c0, float& c1, float& c2, float& c3,
                                         uint32_t a0, uint32_t a1, uint32_t a2, uint32_t a3,
                                         uint32_t b0, uint32_t b1) {
    asm volatile("mma.sync.aligned.m16n8k8.row.col.f32.tf32.tf32.f32 "
                 "{%0,%1,%2,%3}, {%4,%5,%6,%7}, {%8,%9}, {%0,%1,%2,%3};"
                 : "+f"(c0), "+f"(c1), "+f"(c2), "+f"(c3)
                 : "r"(a0), "r"(a1), "r"(a2), "r"(a3), "r"(b0), "r"(b1));
}
__device__ __forceinline__ void cp_async16(uint32_t dst, const void* src) {
    asm volatile("cp.async.cg.shared.global [%0], [%1], 16;" :: "r"(dst), "l"(src));
}
#define CP_COMMIT() asm volatile("cp.async.commit_group;" ::: "memory")
#define CP_WAIT0()  asm volatile("cp.async.wait_group 0;" ::: "memory")

// ---------------------------------------------------------------------------
// Kernel 0: adj -> bitmask
// ---------------------------------------------------------------------------
__global__ __launch_bounds__(64) void adjbits_kernel(const int* __restrict__ adj)
{
    const int row = blockIdx.x, w = threadIdx.x;
    const int4* p = (const int4*)(adj + (size_t)row * NN + w * 32);
    uint32_t bits = 0;
#pragma unroll
    for (int q = 0; q < 8; q++) {
        int4 v = __ldg(p + q);
        bits |= (v.x ? 1u : 0u) << (q * 4 + 0);
        bits |= (v.y ? 1u : 0u) << (q * 4 + 1);
        bits |= (v.z ? 1u : 0u) << (q * 4 + 2);
        bits |= (v.w ? 1u : 0u) << (q * 4 + 3);
    }
    g_adjbits[row * 64 + w] = bits;
}

// ---------------------------------------------------------------------------
// Kernel 0b: Ww -> tf32 B-fragments.
// ---------------------------------------------------------------------------
__global__ __launch_bounds__(256) void wwfrag_kernel(const float* __restrict__ Ww)
{
    const int ks = blockIdx.x, t = threadIdx.x;
    const int lane = t & 31, ntp = t >> 5;
    const int n0 = ntp * 16 + (lane >> 2);
    const int k0 = ks * 8 + (lane & 3);
    g_Wwfrag[ks * 256 + t] = make_uint4(
        f2tf32(__ldg(Ww + (size_t)n0 * FIN + k0)),
        f2tf32(__ldg(Ww + (size_t)n0 * FIN + k0 + 4)),
        f2tf32(__ldg(Ww + (size_t)(n0 + 8) * FIN + k0)),
        f2tf32(__ldg(Ww + (size_t)(n0 + 8) * FIN + k0 + 4)));
}

// ---------------------------------------------------------------------------
// Kernel 1 (fused, TENSOR-CORE): Wh = h @ Ww^T + b via tf32 mma,
// then emit main-GEMM B-fragments + el/er exps. (R16, unchanged)
// ---------------------------------------------------------------------------
__global__ __launch_bounds__(256) void wh_fused_tc(const float* __restrict__ hsrc,
                                                   const float* __restrict__ Wb,
                                                   const float* __restrict__ attn_w)
{
    __shared__ uint32_t hs[32][260];
    __shared__ float    Whs[32][128];
    const int t     = threadIdx.x;
    const int w     = t >> 5;
    const int lane  = t & 31;
    const int mw    = w >> 2;
    const int nw    = w & 3;
    const int r     = lane >> 2;
    const int c     = lane & 3;
    const int grow0 = blockIdx.x * 32;

    {
        const int row = t >> 3;
        const float4* src = (const float4*)(hsrc + (size_t)(grow0 + row) * FIN);
#pragma unroll
        for (int q = 0; q < 8; q++) {
            float4 v = __ldg(src + q * 8 + (t & 7));
            const int col = q * 32 + (t & 7) * 4;
            hs[row][col + 0] = f2tf32(v.x);
            hs[row][col + 1] = f2tf32(v.y);
            hs[row][col + 2] = f2tf32(v.z);
            hs[row][col + 3] = f2tf32(v.w);
        }
    }
    __syncthreads();

    float acc[4][4];
#pragma unroll
    for (int n = 0; n < 4; n++)
#pragma unroll
        for (int k = 0; k < 4; k++) acc[n][k] = 0.f;

    const int mrow = mw * 16 + r;
    const uint4* wwb = g_Wwfrag;

#pragma unroll 8
    for (int ks = 0; ks < FIN / 8; ks++) {
        const int kc = ks * 8 + c;
        uint32_t a0 = hs[mrow][kc];
        uint32_t a1 = hs[mrow + 8][kc];
        uint32_t a2 = hs[mrow][kc + 4];
        uint32_t a3 = hs[mrow + 8][kc + 4];
        uint4 b0 = __ldg(wwb + ks * 256 + (nw * 2 + 0) * 32 + lane);
        uint4 b1 = __ldg(wwb + ks * 256 + (nw * 2 + 1) * 32 + lane);
        mma_tf32(acc[0][0], acc[0][1], acc[0][2], acc[0][3],
                 a0, a1, a2, a3, b0.x, b0.y);
        mma_tf32(acc[1][0], acc[1][1], acc[1][2], acc[1][3],
                 a0, a1, a2, a3, b0.z, b0.w);
        mma_tf32(acc[2][0], acc[2][1], acc[2][2], acc[2][3],
                 a0, a1, a2, a3, b1.x, b1.y);
        mma_tf32(acc[3][0], acc[3][1], acc[3][2], acc[3][3],
                 a0, a1, a2, a3, b1.z, b1.w);
    }

#pragma unroll
    for (int nt = 0; nt < 4; nt++) {
        const int col = nw * 32 + nt * 8 + c * 2;
        float2 bias = *(const float2*)(Wb + col);
        Whs[mrow][col + 0]     = acc[nt][0] + bias.x;
        Whs[mrow][col + 1]     = acc[nt][1] + bias.y;
        Whs[mrow + 8][col + 0] = acc[nt][2] + bias.x;
        Whs[mrow + 8][col + 1] = acc[nt][3] + bias.y;
    }
    __syncthreads();

    const int b  = grow0 >> 11;
    const int n0 = grow0 & (NN - 1);

    {
        const size_t base = ((size_t)b * (NN / 32) + (n0 >> 5)) * 1024;
#pragma unroll
        for (int q = 0; q < 4; q++) {
            const int s    = q * 256 + t;
            const int ln   = s & 31;
            const int ntp  = (s >> 5) & 7;
            const int ks   = s >> 8;
            const int jl   = ks * 8 + (ln & 3);
            const int o0   = ntp * 16 + (ln >> 2);
            g_Bfrag4[base + s] = make_uint4(f2tf32(Whs[jl][o0]),
                                            f2tf32(Whs[jl + 4][o0]),
                                            f2tf32(Whs[jl][o0 + 8]),
                                            f2tf32(Whs[jl + 4][o0 + 8]));
        }
    }

    {
        float4 al[HH], ar[HH];
#pragma unroll
        for (int hh = 0; hh < HH; hh++) {
            al[hh] = __ldg((const float4*)(attn_w + hh * 2 * FOUT + lane * 4));
            ar[hh] = __ldg((const float4*)(attn_w + hh * 2 * FOUT + FOUT + lane * 4));
        }
#pragma unroll
        for (int rr = 0; rr < 4; rr++) {
            const int rowl = w * 4 + rr;
            const int n    = n0 + rowl;
            float4 v = *(const float4*)&Whs[rowl][lane * 4];
#pragma unroll
            for (int hh = 0; hh < HH; hh++) {
                float sl = v.x * al[hh].x + v.y * al[hh].y
                         + v.z * al[hh].z + v.w * al[hh].w;
                float sr = v.x * ar[hh].x + v.y * ar[hh].y
                         + v.z * ar[hh].z + v.w * ar[hh].w;
#pragma unroll
                for (int off = 16; off > 0; off >>= 1) {
                    sl += __shfl_xor_sync(0xffffffffu, sl, off);
                    sr += __shfl_xor_sync(0xffffffffu, sr, off);
                }
                if (lane == 0) {
                    g_iAC[(b * HH + hh) * NN + n] =
                        make_float2(expf(sl), expf(NEG * sl));
                    g_jEFi[((size_t)(b * NN + n)) * HH + hh] =
                        make_float2(expf(sr), expf(NEG * sr));
                }
            }
        }
    }
}

// ---------------------------------------------------------------------------
// Kernel 2: Z pre-pass v4. Thread (rg = t>>5: 4 rows, jq = t&31).
// SoA smem (conflict-free LDS), 4-row reuse per jEF read, shfl reduction.
// ---------------------------------------------------------------------------
__global__ __launch_bounds__(256) void zsum_kernel()
{
    __shared__ float4 jefE[256];        // 4 KB: E of 4 heads per j
    __shared__ float4 jefF[256];        // 4 KB: F of 4 heads per j
    __shared__ float  zr_s[8][4][4];    // per-warp totals
    const int t   = threadIdx.x;
    const int rg  = t >> 5;             // warp = row group (4 rows)
    const int jq  = t & 31;
    const int b   = blockIdx.y;
    const int i0  = blockIdx.x * 32;

    // row constants for this thread's 4 rows x 4 heads
    float2 AC[4][HH];
#pragma unroll
    for (int rr = 0; rr < 4; rr++)
#pragma unroll
        for (int h = 0; h < HH; h++)
            AC[rr][h] = __ldg(&g_iAC[(b * HH + h) * NN + i0 + rg * 4 + rr]);

    const uint32_t* mrow[4];
#pragma unroll
    for (int rr = 0; rr < 4; rr++)
        mrow[rr] = g_adjbits + (size_t)(i0 + rg * 4 + rr) * 64;

    float z[4][HH];
#pragma unroll
    for (int rr = 0; rr < 4; rr++)
#pragma unroll
        for (int h = 0; h < HH; h++) z[rr][h] = 0.f;

    const float4* src4 = (const float4*)(g_jEFi + (size_t)b * NN * HH);

    for (int c0 = 0; c0 < NN; c0 += 256) {
        __syncthreads();
        {   // stage 256 j, permute AoS (E0,F0,E1,F1),(E2,F2,E3,F3) -> SoA
            float4 v0 = __ldg(src4 + (size_t)(c0 + t) * 2);
            float4 v1 = __ldg(src4 + (size_t)(c0 + t) * 2 + 1);
            jefE[t] = make_float4(v0.x, v0.z, v1.x, v1.z);
            jefF[t] = make_float4(v0.y, v0.w, v1.y, v1.w);
        }
        __syncthreads();

        const int w0 = c0 >> 5;
#pragma unroll
        for (int hf = 0; hf < 2; hf++) {
            uint4 mv[4];
#pragma unroll
            for (int rr = 0; rr < 4; rr++)
                mv[rr] = __ldg((const uint4*)(mrow[rr] + w0 + hf * 4));
#pragma unroll
            for (int e2 = 0; e2 < 4; e2++) {
                const int e = hf * 4 + e2;
                float4 E = jefE[e * 32 + jq];
                float4 F = jefF[e * 32 + jq];
#pragma unroll
                for (int rr = 0; rr < 4; rr++) {
                    const uint32_t mwd = (e2 == 0) ? mv[rr].x :
                                         (e2 == 1) ? mv[rr].y :
                                         (e2 == 2) ? mv[rr].z : mv[rr].w;
                    if ((mwd >> jq) & 1u) {
                        z[rr][0] += fmaxf(AC[rr][0].x * E.x, AC[rr][0].y * F.x);
                        z[rr][1] += fmaxf(AC[rr][1].x * E.y, AC[rr][1].y * F.y);
                        z[rr][2] += fmaxf(AC[rr][2].x * E.z, AC[rr][2].y * F.z);
                        z[rr][3] += fmaxf(AC[rr][3].x * E.w, AC[rr][3].y * F.w);
                    }
                }
            }
        }
    }

    // warp-level reduction over jq lanes
#pragma unroll
    for (int rr = 0; rr < 4; rr++)
#pragma unroll
        for (int h = 0; h < HH; h++) {
            float v = z[rr][h];
            v += __shfl_xor_sync(0xffffffffu, v, 1);
            v += __shfl_xor_sync(0xffffffffu, v, 2);
            v += __shfl_xor_sync(0xffffffffu, v, 4);
            v += __shfl_xor_sync(0xffffffffu, v, 8);
            v += __shfl_xor_sync(0xffffffffu, v, 16);
            z[rr][h] = v;
        }
    if (jq == 0) {
#pragma unroll
        for (int rr = 0; rr < 4; rr++)
#pragma unroll
            for (int h = 0; h < HH; h++)
                zr_s[rg][rr][h] = z[rr][h];
    }
    __syncthreads();

    if (t < 128) {
        const int rg2 = t >> 4, rr = (t >> 2) & 3, h = t & 3;
        const int row = i0 + rg2 * 4 + rr;
        float Z = zr_s[rg2][rr][h];
        float2 ac  = __ldg(&g_iAC[(b * HH + h) * NN + row]);
        float  inv = (Z > 0.f) ? 0.25f / Z : 0.f;
        g_irow[(b * HH + h) * NN + row] = make_float2(ac.x * inv, ac.y * inv);
    }
}

// ---------------------------------------------------------------------------
// Kernel 3 (main): P_avg @ Wh via mma.sync tf32, M=32, TK=32/iter. (R10 best)
// ---------------------------------------------------------------------------
#define SM_A(mt, ks, ln)    (((mt) * 4 + (ks)) * 32 + (ln))
#define SM_B(p, ks, ntp, ln) ((p) * 1024 + (ks) * 256 + (ntp) * 32 + (ln))
#define OFF_BF 4096
#define OFF_JP 36864
#define SMEM_BYTES 38912

__global__ __launch_bounds__(256, 3) void gat_main_mma(float* __restrict__ out)
{
    extern __shared__ char smem[];
    uint4*  Af  = (uint4*)smem;
    uint4*  Bf  = (uint4*)(smem + OFF_BF);
    float4* JPf = (float4*)(smem + OFF_JP);
    const uint32_t Bf_sa = (uint32_t)__cvta_generic_to_shared(Bf);
    const uint32_t JP_sa = (uint32_t)__cvta_generic_to_shared(JPf);

    const int t    = threadIdx.x;
    const int w    = t >> 5;
    const int lane = t & 31;
    const int mw   = w >> 2;
    const int nw   = w & 3;
    const int b    = blockIdx.y;
    const int i0   = blockIdx.x * 32;

    const int r = lane >> 2;
    const int c = lane & 3;

    const int gia = i0 + mw * 16 + r;
    const int gib = gia + 8;

    float2 RA[4], RB[4];
#pragma unroll
    for (int h = 0; h < HH; h++) {
        RA[h] = __ldg(&g_irow[(b * HH + h) * NN + gia]);
        RB[h] = __ldg(&g_irow[(b * HH + h) * NN + gib]);
    }
    const uint32_t* mba   = g_adjbits + (size_t)gia * 64;
    const uint32_t* mbb   = g_adjbits + (size_t)gib * 64;
    const uint4*    bbase = g_Bfrag4 + (size_t)b * (NN / 32) * 1024;
    const float4*   jsrc  = (const float4*)(g_jEFi + (size_t)b * NN * HH);

    float acc[4][4];
#pragma unroll
    for (int n = 0; n < 4; n++)
#pragma unroll
        for (int k = 0; k < 4; k++) acc[n][k] = 0.f;

    auto stage = [&](int jn, int q) {
        const uint4* src = bbase + (size_t)jn * 1024;
        const uint32_t bdst = Bf_sa + (uint32_t)q * 16384u;
#pragma unroll
        for (int k4 = 0; k4 < 4; k4++)
            cp_async16(bdst + (uint32_t)(k4 * 256 + t) * 16u, src + k4 * 256 + t);
        if (t < 64)
            cp_async16(JP_sa + (uint32_t)(q * 64 + t) * 16u, jsrc + jn * 64 + t);
        CP_COMMIT();
    };

    auto agen = [&](int p, uint32_t ma, uint32_t mb2) {
        const float4* JP = JPf + p * 64;
        const int jA = nw * 8 + c;
        float4 a01 = JP[jA * 2],       a23 = JP[jA * 2 + 1];
        float4 b01 = JP[(jA + 4) * 2], b23 = JP[(jA + 4) * 2 + 1];

        float vaA = (fmaxf(RA[0].x * a01.x, RA[0].y * a01.y)
                   + fmaxf(RA[1].x * a01.z, RA[1].y * a01.w))
                  + (fmaxf(RA[2].x * a23.x, RA[2].y * a23.y)
                   + fmaxf(RA[3].x * a23.z, RA[3].y * a23.w));
        float vbA = (fmaxf(RB[0].x * a01.x, RB[0].y * a01.y)
                   + fmaxf(RB[1].x * a01.z, RB[1].y * a01.w))
                  + (fmaxf(RB[2].x * a23.x, RB[2].y * a23.y)
                   + fmaxf(RB[3].x * a23.z, RB[3].y * a23.w));
        float vaB = (fmaxf(RA[0].x * b01.x, RA[0].y * b01.y)
                   + fmaxf(RA[1].x * b01.z, RA[1].y * b01.w))
                  + (fmaxf(RA[2].x * b23.x, RA[2].y * b23.y)
                   + fmaxf(RA[3].x * b23.z, RA[3].y * b23.w));
        float vbB = (fmaxf(RB[0].x * b01.x, RB[0].y * b01.y)
                   + fmaxf(RB[1].x * b01.z, RB[1].y * b01.w))
                  + (fmaxf(RB[2].x * b23.x, RB[2].y * b23.y)
                   + fmaxf(RB[3].x * b23.z, RB[3].y * b23.w));

        const int sh = nw * 8 + c;
        vaA = ((ma  >> sh)       & 1u) ? vaA : 0.f;
        vbA = ((mb2 >> sh)       & 1u) ? vbA : 0.f;
        vaB = ((ma  >> (sh + 4)) & 1u) ? vaB : 0.f;
        vbB = ((mb2 >> (sh + 4)) & 1u) ? vbB : 0.f;

        Af[SM_A(mw, nw, lane)] =
            make_uint4(f2tf32(vaA), f2tf32(vbA), f2tf32(vaB), f2tf32(vbB));
    };

    auto consume = [&](int p) {
#pragma unroll
        for (int ks = 0; ks < 4; ks++) {
            uint4 a  = Af[SM_A(mw, ks, lane)];
            uint4 b0 = Bf[SM_B(p, ks, nw * 2 + 0, lane)];
            uint4 b1 = Bf[SM_B(p, ks, nw * 2 + 1, lane)];
            mma_tf32(acc[0][0], acc[0][1], acc[0][2], acc[0][3],
                     a.x, a.y, a.z, a.w, b0.x, b0.y);
            mma_tf32(acc[1][0], acc[1][1], acc[1][2], acc[1][3],
                     a.x, a.y, a.z, a.w, b0.z, b0.w);
            mma_tf32(acc[2][0], acc[2][1], acc[2][2], acc[2][3],
                     a.x, a.y, a.z, a.w, b1.x, b1.y);
            mma_tf32(acc[3][0], acc[3][1], acc[3][2], acc[3][3],
                     a.x, a.y, a.z, a.w, b1.z, b1.w);
        }
    };

    stage(0, 0);
    uint32_t maC = __ldg(mba + 0);
    uint32_t mbC = __ldg(mbb + 0);
    CP_WAIT0();
    __syncthreads();

    for (int jt = 0; jt < NI; jt++) {
        const int p = jt & 1, q = p ^ 1;

        if (jt + 1 < NI) stage(jt + 1, q);

        agen(p, maC, mbC);
        __syncthreads();

        consume(p);

        if (jt + 1 < NI) {
            maC = __ldg(mba + jt + 1);
            mbC = __ldg(mbb + jt + 1);
            CP_WAIT0();
        }
        __syncthreads();
    }

    const int rowa = i0 + mw * 16 + r;
#pragma unroll
    for (int nt = 0; nt < 4; nt++) {
        const int col = nw * 32 + nt * 8 + c * 2;
        float* op = out + ((size_t)(b * NN + rowa)) * FOUT + col;
        *(float2*)op = make_float2(fmaxf(acc[nt][0], 0.f), fmaxf(acc[nt][1], 0.f));
        *(float2*)(op + 8 * FOUT) = make_float2(fmaxf(acc[nt][2], 0.f),
                                                fmaxf(acc[nt][3], 0.f));
    }
}

// ---------------------------------------------------------------------------
extern "C" void kernel_launch(void* const* d_in, const int* in_sizes, int n_in,
                              void* d_out, int out_size)
{
    const float* h      = (const float*)d_in[0];
    const int*   adj    = (const int*)d_in[1];
    const float* W_w    = (const float*)d_in[2];
    const float* W_b    = (const float*)d_in[3];
    const float* attn_w = (const float*)d_in[4];
    float* out = (float*)d_out;

    adjbits_kernel<<<NN, 64>>>(adj);
    wwfrag_kernel<<<FIN / 8, 256>>>(W_w);
    wh_fused_tc<<<(Bb * NN) / 32, 256>>>(h, W_b, attn_w);
    zsum_kernel<<<dim3(NN / 32, Bb), 256>>>();

    cudaFuncSetAttribute(gat_main_mma,
                         cudaFuncAttributeMaxDynamicSharedMemorySize, SMEM_BYTES);
    gat_main_mma<<<dim3(NN / 32, Bb), 256, SMEM_BYTES>>>(out);
}